// round 3
// baseline (speedup 1.0000x reference)
#include <cuda_runtime.h>
#include <cstdint>

#define B_ 64
#define S_ 512
#define H_ 768
#define L_ 9
#define NPAIR 254          // pairs p=0..253 cover steps 1..508
#define NQUAD 127          // quads q=0..126 cover steps 1..508
#define G4STRIDE 10288     // 127*81 = 10287, padded to /4
#define LOG2E 1.4426950408889634f
#define LN2f  0.6931471805599453f

// device scratch (no allocations allowed)
__device__ float g_feats[B_ * S_ * L_];
__device__ float g_fexp [B_ * S_ * L_];
__device__ float g_P    [B_ * NPAIR * 81];
__device__ float g_G4   [B_ * G4STRIDE];
__device__ float g_res  [B_];

__device__ __forceinline__ float ex2f(float x) {
    float y; asm("ex2.approx.f32 %0, %1;" : "=f"(y) : "f"(x)); return y;
}
__device__ __forceinline__ float lg2f_(float x) {
    float y; asm("lg2.approx.f32 %0, %1;" : "=f"(y) : "f"(x)); return y;
}
__device__ __forceinline__ void ffma2(unsigned long long& d,
                                      unsigned long long a,
                                      unsigned long long b) {
    asm("fma.rn.f32x2 %0, %1, %2, %0;" : "+l"(d) : "l"(a), "l"(b));
}
__device__ __forceinline__ float warp_sum(float v) {
    v += __shfl_xor_sync(0xffffffffu, v, 16);
    v += __shfl_xor_sync(0xffffffffu, v, 8);
    v += __shfl_xor_sync(0xffffffffu, v, 4);
    v += __shfl_xor_sync(0xffffffffu, v, 2);
    v += __shfl_xor_sync(0xffffffffu, v, 1);
    return v;
}
__device__ __forceinline__ int warp_sum_i(int v) {
    v += __shfl_xor_sync(0xffffffffu, v, 16);
    v += __shfl_xor_sync(0xffffffffu, v, 8);
    v += __shfl_xor_sync(0xffffffffu, v, 4);
    v += __shfl_xor_sync(0xffffffffu, v, 2);
    v += __shfl_xor_sync(0xffffffffu, v, 1);
    return v;
}

// ---------------------------------------------------------------------------
// K1: feats[b,s,l] = hidden[b,s,:] . W[l,:] + bias[l]; also fexp = exp(feats).
// 256 threads; each warp does 4 rows; W in SMEM; fma.rn.f32x2 packed FMAs.
// DRAM-bound (~100MB of hidden).
// ---------------------------------------------------------------------------
__global__ __launch_bounds__(256) void feats_kernel(
        const float* __restrict__ hidden,
        const float* __restrict__ W,
        const float* __restrict__ bias) {
    __shared__ __align__(16) float Ws[L_ * H_];
    int tid = threadIdx.x;
    for (int i = tid; i < L_ * H_; i += 256) Ws[i] = W[i];
    __syncthreads();

    int warp = tid >> 5, lane = tid & 31;
    int rbase = blockIdx.x * 32 + warp * 4;

    unsigned long long acc2[4][9];
#pragma unroll
    for (int r = 0; r < 4; r++)
#pragma unroll
        for (int l = 0; l < 9; l++) acc2[r][l] = 0ull;

#pragma unroll
    for (int c = 0; c < 6; c++) {
        int h = c * 128 + lane * 4;
        ulonglong2 hv[4];
#pragma unroll
        for (int r = 0; r < 4; r++)
            hv[r] = *reinterpret_cast<const ulonglong2*>(
                        hidden + (size_t)(rbase + r) * H_ + h);
#pragma unroll
        for (int l = 0; l < 9; l++) {
            ulonglong2 wv = *reinterpret_cast<const ulonglong2*>(&Ws[l * H_ + h]);
#pragma unroll
            for (int r = 0; r < 4; r++) {
                ffma2(acc2[r][l], hv[r].x, wv.x);
                ffma2(acc2[r][l], hv[r].y, wv.y);
            }
        }
    }

    float acc[4][9];
#pragma unroll
    for (int r = 0; r < 4; r++)
#pragma unroll
        for (int l = 0; l < 9; l++) {
            float lo = __uint_as_float((unsigned)(acc2[r][l] & 0xffffffffull));
            float hi = __uint_as_float((unsigned)(acc2[r][l] >> 32));
            acc[r][l] = warp_sum(lo + hi);   // all lanes hold the sum
        }

    // lane l writes tag l for all 4 rows (static indexing, predicated)
#pragma unroll
    for (int l = 0; l < 9; l++) {
        if (lane == l) {
#pragma unroll
            for (int r = 0; r < 4; r++) {
                float v = acc[r][l] + bias[l];
                size_t o = (size_t)(rbase + r) * L_ + l;
                g_feats[o] = v;
                g_fexp[o]  = ex2f(v * LOG2E);
            }
        }
    }
}

// ---------------------------------------------------------------------------
// K2: pair operators. P_p[i][j] = (sum_k E[i][k]*f_{2p+1}[k]*E[k][j]) * f_{2p+2}[j]
// One thread per (b,p). E = exp(trans) staged in SMEM (broadcast reads).
// ---------------------------------------------------------------------------
__global__ __launch_bounds__(256) void pairs_kernel(const float* __restrict__ trans) {
    __shared__ float Es[81];
    int b = blockIdx.x, p = threadIdx.x;
    if (p < 81) Es[p] = ex2f(trans[p] * LOG2E);
    __syncthreads();
    if (p >= NPAIR) return;

    const float* f1 = g_fexp + ((size_t)b * S_ + (2 * p + 1)) * L_;
    const float* f2 = g_fexp + ((size_t)b * S_ + (2 * p + 2)) * L_;
    float f1r[9], f2r[9];
#pragma unroll
    for (int k = 0; k < 9; k++) { f1r[k] = f1[k]; f2r[k] = f2[k]; }

    float* P = g_P + ((size_t)b * NPAIR + p) * 81;
#pragma unroll
    for (int i = 0; i < 9; i++) {
        float t[9];
#pragma unroll
        for (int k = 0; k < 9; k++) t[k] = Es[i * 9 + k] * f1r[k];
#pragma unroll
        for (int jj = 0; jj < 9; jj++) {
            float s = t[0] * Es[0 * 9 + jj];
#pragma unroll
            for (int k = 1; k < 9; k++) s = fmaf(t[k], Es[k * 9 + jj], s);
            P[i * 9 + jj] = s * f2r[jj];
        }
    }
}

// ---------------------------------------------------------------------------
// K3: quad operators. G_q = P_{2q} * P_{2q+1} (row-vector convention).
// One thread per (b,q); P_{2q+1} staged in a per-thread SMEM slice.
// ---------------------------------------------------------------------------
__global__ __launch_bounds__(128) void quads_kernel() {
    __shared__ float Ps[128 * 81];
    int b = blockIdx.x, q = threadIdx.x;
    if (q >= NQUAD) return;

    const float* P0 = g_P + ((size_t)b * NPAIR + 2 * q) * 81;
    const float* P1 = g_P + ((size_t)b * NPAIR + 2 * q + 1) * 81;
    float* ps = Ps + q * 81;
#pragma unroll 9
    for (int e = 0; e < 81; e++) ps[e] = P1[e];

    float* G = g_G4 + (size_t)b * G4STRIDE + q * 81;
#pragma unroll
    for (int i = 0; i < 9; i++) {
        float row[9];
#pragma unroll
        for (int m = 0; m < 9; m++) row[m] = P0[i * 9 + m];
#pragma unroll
        for (int jj = 0; jj < 9; jj++) {
            float s = row[0] * ps[0 * 9 + jj];
#pragma unroll
            for (int m = 1; m < 9; m++) s = fmaf(row[m], ps[m * 9 + jj], s);
            G[i * 9 + jj] = s;
        }
    }
}

// ---------------------------------------------------------------------------
// K4: serial CRF scan over quad operators (warp 0) + gold score (warp 1).
// Lane (j = lane%9, g = lane/9) holds a[3g..3g+2]; per quad:
//  s = a.G partials -> 3-way butterfly SHFL -> sum -> redistribute SHFL,
//  per-quad exponent renorm by tag0 (int base-2 accumulator C2).
// G staged in SMEM, register-prefetched one quad ahead.
// <=3 leftover single steps use E=exp(trans) + fexp directly.
// ---------------------------------------------------------------------------
__global__ __launch_bounds__(64) void crf_kernel(
        const float* __restrict__ start_t,
        const float* __restrict__ end_t,
        const float* __restrict__ trans,
        const int*   __restrict__ labels,
        const void*  __restrict__ mask_raw) {
    __shared__ __align__(16) float Gs[128 * 81];   // 10368 floats (127 quads + prefetch pad)
    __shared__ float score_sh;

    int b = blockIdx.x;
    int tid = threadIdx.x, lane = tid & 31, warp = tid >> 5;
    const float* feats = g_feats + (size_t)b * (S_ * L_);

    // stage this batch's quads (10288 floats incl. pad word; rest of Gs unread-garbage)
    {
        const float4* src = reinterpret_cast<const float4*>(g_G4 + (size_t)b * G4STRIDE);
        float4* dst = reinterpret_cast<float4*>(Gs);
        for (int i = tid; i < G4STRIDE / 4; i += 64) dst[i] = src[i];
    }

    // sequence length with mask-dtype runtime detection.
    // mask[0][0..3] are all 1 (len >= S/2):
    //   uint8/bool -> first word 0x01010101 ; int32 -> 1 ; float32 -> 0x3F800000
    unsigned w0 = *reinterpret_cast<const unsigned*>(mask_raw);
    int cnt = 0;
    if (w0 == 0x3F800000u) {
        const float* mb = reinterpret_cast<const float*>(mask_raw) + b * S_;
        for (int t = lane; t < S_; t += 32) cnt += (mb[t] != 0.0f);
    } else if (w0 > 1u) {
        const unsigned char* mb = reinterpret_cast<const unsigned char*>(mask_raw) + b * S_;
        for (int t = lane; t < S_; t += 32) cnt += (mb[t] != 0);
    } else {
        const int* mb = reinterpret_cast<const int*>(mask_raw) + b * S_;
        for (int t = lane; t < S_; t += 32) cnt += (mb[t] != 0);
    }
    int len = warp_sum_i(cnt);
    __syncthreads();

    float log_den = 0.f;
    if (warp == 0) {
        int j = lane % 9;
        int g = lane / 9;                    // 0..2 active, 3 inert
        bool active = lane < 27;
        int i0 = min(3 * g + 0, 8);
        int i1 = min(3 * g + 1, 8);
        int i2 = min(3 * g + 2, 8);
        int e0 = i0 * 9 + j, e1 = i1 * 9 + j, e2 = i2 * 9 + j;

        float E0 = 0.f, E1 = 0.f, E2 = 0.f;
        float a0 = 0.f, a1 = 0.f, a2 = 0.f;
        if (active) {
            E0 = ex2f(trans[e0] * LOG2E);
            E1 = ex2f(trans[e1] * LOG2E);
            E2 = ex2f(trans[e2] * LOG2E);
            const float* f0 = g_fexp + (size_t)b * (S_ * L_);
            a0 = f0[i0] * ex2f(start_t[i0] * LOG2E);
            a1 = f0[i1] * ex2f(start_t[i1] * LOG2E);
            a2 = f0[i2] * ex2f(start_t[i2] * LOG2E);
        }
        float Ee0 = ex2f(end_t[i0] * LOG2E);
        float Ee1 = ex2f(end_t[i1] * LOG2E);
        float Ee2 = ex2f(end_t[i2] * LOG2E);

        int nsteps = len - 1;                // 255..511
        int nq = nsteps >> 2;                // quads to apply (<=127)
        int rem = nsteps & 3;                // leftover singles

        // prefetch leftover emission factors fexp[t][j]
        float fl0 = 0.f, fl1 = 0.f, fl2 = 0.f;
        {
            const float* fx = g_fexp + (size_t)b * (S_ * L_);
            int t0 = 4 * nq + 1;
            if (rem > 0) fl0 = fx[(t0 + 0) * L_ + j];
            if (rem > 1) fl1 = fx[(t0 + 1) * L_ + j];
            if (rem > 2) fl2 = fx[(t0 + 2) * L_ + j];
        }

        int C2 = 0;
        float G0 = Gs[e0], G1 = Gs[e1], G2 = Gs[e2];
        int base = 81;
        for (int q = 0; q < nq; q++) {
            float s = fmaf(a2, G2, fmaf(a1, G1, a0 * G0));
            float nG0 = Gs[base + e0];       // prefetch next quad (pad-safe)
            float nG1 = Gs[base + e1];
            float nG2 = Gs[base + e2];
            base += 81;
            float sA = __shfl_sync(0xffffffffu, s, j);
            float sB = __shfl_sync(0xffffffffu, s, j + 9);
            float sC = __shfl_sync(0xffffffffu, s, j + 18);
            float u = (sA + sB) + sC;
            float u0 = __shfl_sync(0xffffffffu, u, 0);
            float n0 = __shfl_sync(0xffffffffu, u, i0);
            float n1 = __shfl_sync(0xffffffffu, u, i1);
            float n2 = __shfl_sync(0xffffffffu, u, i2);
            unsigned eb = (__float_as_uint(u0) >> 23) & 0xFFu;
            C2 += (int)eb - 127;
            float scale = __uint_as_float((254u - eb) << 23);
            a0 = n0 * scale; a1 = n1 * scale; a2 = n2 * scale;
            G0 = nG0; G1 = nG1; G2 = nG2;
        }

#define CRF_SINGLE(F)                                                        \
        {                                                                    \
            float s = fmaf(a2, E2, fmaf(a1, E1, a0 * E0));                   \
            float sA = __shfl_sync(0xffffffffu, s, j);                       \
            float sB = __shfl_sync(0xffffffffu, s, j + 9);                   \
            float sC = __shfl_sync(0xffffffffu, s, j + 18);                  \
            float u = ((sA + sB) + sC) * (F);                                \
            float n0 = __shfl_sync(0xffffffffu, u, i0);                      \
            float n1 = __shfl_sync(0xffffffffu, u, i1);                      \
            float n2 = __shfl_sync(0xffffffffu, u, i2);                      \
            a0 = n0; a1 = n1; a2 = n2;                                       \
        }
        if (rem > 0) CRF_SINGLE(fl0)
        if (rem > 1) CRF_SINGLE(fl1)
        if (rem > 2) CRF_SINGLE(fl2)
#undef CRF_SINGLE

        // log_den = ln2 * (C2 + log2(sum_i a_i * exp(end_i)))
        // each i appears in 9 lanes (one per j) -> divide by 9 (exact math).
        float ef = 0.f;
        if (active) ef = fmaf(a2, Ee2, fmaf(a1, Ee1, a0 * Ee0));
        ef = warp_sum(ef);
        log_den = ((float)C2 + lg2f_(ef * (1.0f / 9.0f))) * LN2f;
    } else {
        // gold path score (natural log domain, raw feats)
        const int* lab = labels + b * S_;
        float s = 0.f;
#pragma unroll
        for (int k = 0; k < S_ / 32; k++) {
            int t = k * 32 + lane;
            if (t >= 1 && t < len) {
                int lp = lab[t - 1], lt = lab[t];
                s += trans[lp * L_ + lt] + feats[t * L_ + lt];
            }
        }
        s = warp_sum(s);
        if (lane == 0) {
            int l0 = lab[0];
            int ll = lab[len - 1];
            s += start_t[l0] + feats[l0] + end_t[ll];
            score_sh = s;
        }
    }
    __syncthreads();
    if (tid == 0) g_res[b] = log_den - score_sh;
}

// ---------------------------------------------------------------------------
// K5: deterministic final mean over 64 batches.
// ---------------------------------------------------------------------------
__global__ __launch_bounds__(32) void reduce_kernel(float* __restrict__ out) {
    int lane = threadIdx.x;
    float v = g_res[lane] + g_res[lane + 32];
    v = warp_sum(v);
    if (lane == 0) out[0] = v * (1.0f / 64.0f);
}

extern "C" void kernel_launch(void* const* d_in, const int* in_sizes, int n_in,
                              void* d_out, int out_size) {
    const float* hidden  = (const float*)d_in[0];
    const float* W       = (const float*)d_in[1];
    const float* bias    = (const float*)d_in[2];
    const float* start_t = (const float*)d_in[3];
    const float* end_t   = (const float*)d_in[4];
    const float* trans   = (const float*)d_in[5];
    const int*   labels  = (const int*)d_in[6];
    const void*  mask    = (const void*)d_in[7];

    feats_kernel<<<(B_ * S_) / 32, 256>>>(hidden, W, bias);
    pairs_kernel<<<B_, 256>>>(trans);
    quads_kernel<<<B_, 128>>>();
    crf_kernel<<<B_, 64>>>(start_t, end_t, trans, labels, mask);
    reduce_kernel<<<1, 32>>>((float*)d_out);
}

// round 8
// speedup vs baseline: 1.4502x; 1.4502x over previous
#include <cuda_runtime.h>
#include <cstdint>

#define B_ 64
#define S_ 512
#define H_ 768
#define L_ 9
#define NLEAF 256          // pair leaves: leaf u covers steps 2u+1, 2u+2
#define RSTR 12            // padded row stride (floats) -> float4-aligned rows
#define MSTR 112           // padded matrix stride (floats), 16B-aligned
#define PSTR 257           // partials stride (floats) -> conflict-free smem
#define LOG2E 1.4426950408889634f
#define LN2f  0.6931471805599453f

// dynamic smem layout for crf_kernel (floats):
//   fx  : 512*9        staged fexp for this batch (coalesced copy-in)
//   Ms  : 256*112      pair/product matrices (9x9 padded to 12-float rows)
//   sc  : 256 ints     renorm exponent accumulators
//   keA : 128 ints     per-level scale factors
//   Es  : 81           exp(trans)
//   misc: [0]=len (int), [1]=score, [2]=log_den
#define SMEM_BYTES (S_ * L_ * 4 + NLEAF * MSTR * 4 + NLEAF * 4 + 128 * 4 + 81 * 4 + 16)

// device scratch (no allocations allowed)
__device__ float g_feats[B_ * S_ * L_];
__device__ float g_fexp [B_ * S_ * L_];
__device__ float g_res  [B_];
__device__ unsigned g_arrive = 0;

__device__ __forceinline__ float ex2f(float x) {
    float y; asm("ex2.approx.f32 %0, %1;" : "=f"(y) : "f"(x)); return y;
}
__device__ __forceinline__ float lg2f_(float x) {
    float y; asm("lg2.approx.f32 %0, %1;" : "=f"(y) : "f"(x)); return y;
}
__device__ __forceinline__ void ffma2(unsigned long long& d,
                                      unsigned long long a,
                                      unsigned long long b) {
    asm("fma.rn.f32x2 %0, %1, %2, %0;" : "+l"(d) : "l"(a), "l"(b));
}
__device__ __forceinline__ float warp_sum(float v) {
    v += __shfl_xor_sync(0xffffffffu, v, 16);
    v += __shfl_xor_sync(0xffffffffu, v, 8);
    v += __shfl_xor_sync(0xffffffffu, v, 4);
    v += __shfl_xor_sync(0xffffffffu, v, 2);
    v += __shfl_xor_sync(0xffffffffu, v, 1);
    return v;
}
__device__ __forceinline__ int warp_sum_i(int v) {
    v += __shfl_xor_sync(0xffffffffu, v, 16);
    v += __shfl_xor_sync(0xffffffffu, v, 8);
    v += __shfl_xor_sync(0xffffffffu, v, 4);
    v += __shfl_xor_sync(0xffffffffu, v, 2);
    v += __shfl_xor_sync(0xffffffffu, v, 1);
    return v;
}
// load 9 floats of a padded 16B-aligned row: 2x float4 + 1 scalar
__device__ __forceinline__ void ldrow9(const float* __restrict__ p, float* r) {
    float4 a = *reinterpret_cast<const float4*>(p);
    float4 b = *reinterpret_cast<const float4*>(p + 4);
    r[0] = a.x; r[1] = a.y; r[2] = a.z; r[3] = a.w;
    r[4] = b.x; r[5] = b.y; r[6] = b.z; r[7] = b.w;
    r[8] = p[8];
}

// ---------------------------------------------------------------------------
// K1: feats[b,s,l] = hidden[b,s,:] . W[l,:] + bias[l]; also fexp = exp(feats).
// 256 threads; each warp does 4 rows (32 rows/block); W in SMEM;
// fma.rn.f32x2 packed FMAs. Epilogue = SMEM transpose-reduce (no butterfly):
// each thread stores 36 partials, then one thread per (row,tag) output sums
// 32 lanes sequentially (deterministic) and writes feats + fexp.
// Ws and partials share one static SMEM buffer (disjoint in time).
// ---------------------------------------------------------------------------
__global__ __launch_bounds__(256) void feats_kernel(
        const float* __restrict__ hidden,
        const float* __restrict__ W,
        const float* __restrict__ bias) {
    __shared__ __align__(16) float sbuf[36 * PSTR + 4];  // >= max(Ws, partials)
    float* Ws   = sbuf;        // phase A: 9*768 = 6912 floats
    float* part = sbuf;        // phase B: 36*257 floats

    int tid = threadIdx.x;
    for (int i = tid; i < L_ * H_; i += 256) Ws[i] = W[i];
    __syncthreads();

    int warp = tid >> 5, lane = tid & 31;
    int rbase = blockIdx.x * 32 + warp * 4;

    unsigned long long acc2[4][9];
#pragma unroll
    for (int r = 0; r < 4; r++)
#pragma unroll
        for (int l = 0; l < 9; l++) acc2[r][l] = 0ull;

#pragma unroll
    for (int c = 0; c < 6; c++) {
        int h = c * 128 + lane * 4;
        ulonglong2 hv[4];
#pragma unroll
        for (int r = 0; r < 4; r++)
            hv[r] = *reinterpret_cast<const ulonglong2*>(
                        hidden + (size_t)(rbase + r) * H_ + h);
#pragma unroll
        for (int l = 0; l < 9; l++) {
            ulonglong2 wv = *reinterpret_cast<const ulonglong2*>(&Ws[l * H_ + h]);
#pragma unroll
            for (int r = 0; r < 4; r++) {
                ffma2(acc2[r][l], hv[r].x, wv.x);
                ffma2(acc2[r][l], hv[r].y, wv.y);
            }
        }
    }
    __syncthreads();   // everyone done reading Ws; safe to overwrite with partials

    // store 36 per-thread partials (lo+hi fold of the packed accumulator)
#pragma unroll
    for (int r = 0; r < 4; r++)
#pragma unroll
        for (int l = 0; l < 9; l++) {
            float lo = __uint_as_float((unsigned)(acc2[r][l] & 0xffffffffull));
            float hi = __uint_as_float((unsigned)(acc2[r][l] >> 32));
            part[(r * 9 + l) * PSTR + tid] = lo + hi;
        }
    __syncthreads();

    // 288 outputs; thread handles o = tid and (if tid<32) o = 256+tid
#pragma unroll
    for (int rep = 0; rep < 2; rep++) {
        int o = rep * 256 + tid;
        if (o < 288) {
            int w = o / 36, idx = o - w * 36;
            int r = idx / 9, l = idx - r * 9;
            const float* p = part + idx * PSTR + w * 32;
            float s = p[0];
#pragma unroll
            for (int k = 1; k < 32; k++) s += p[k];
            float v = s + bias[l];
            size_t off = (size_t)(blockIdx.x * 32 + w * 4 + r) * L_ + l;
            g_feats[off] = v;
            g_fexp[off]  = ex2f(v * LOG2E);
        }
    }
}

// ---------------------------------------------------------------------------
// K2: fused CRF via parallel binary tree over PAIR operators + final mean.
//   M_t[i][j] = exp(trans[i][j]) * fexp[t][j]  for t=1..len-1, identity after.
//   Leaf u (one thread each) = M_{2u+1} * M_{2u+2}, built in registers from
//   SMEM-staged fexp. 8 in-place reduction levels in SMEM (rows padded to
//   12 floats -> float4 LDS); per-matrix base-2 renorm via exponent proxy
//   (read-only pre-pass per level -> race-free).
//   log_den = ln( a0^T * root * exp(end) ),  a0 = fexp[0] * exp(start).
//   Warp 1 computes the gold-path score. Last-arriving block does the mean
//   over g_res (threadfence-reduction pattern; fixed order => deterministic).
// ---------------------------------------------------------------------------
__global__ __launch_bounds__(256) void crf_kernel(
        const float* __restrict__ start_t,
        const float* __restrict__ end_t,
        const float* __restrict__ trans,
        const int*   __restrict__ labels,
        const void*  __restrict__ mask_raw,
        float* __restrict__ out) {
    extern __shared__ __align__(16) float smem[];
    float* fx  = smem;                               // 512*9
    float* Ms  = fx + S_ * L_;                       // 256*112 (padded)
    int*   sc  = (int*)(Ms + NLEAF * MSTR);          // 256
    int*   keA = sc + NLEAF;                         // 128
    float* Es  = (float*)(keA + 128);                // 81
    float* misc = Es + 81;                           // [0]=len,[1]=score,[2]=lden

    int b = blockIdx.x;
    int tid = threadIdx.x, lane = tid & 31, warp = tid >> 5;
    const float* fexp_b = g_fexp + (size_t)b * (S_ * L_);

    // stage fexp for this batch (coalesced float4)
    {
        const float4* src = reinterpret_cast<const float4*>(fexp_b);
        float4* dst = reinterpret_cast<float4*>(fx);
        for (int i = tid; i < (S_ * L_) / 4; i += 256) dst[i] = src[i];
    }

    // E = exp(trans) (threads 0..80)
    if (tid < 81) Es[tid] = ex2f(trans[tid] * LOG2E);

    // sequence length (warp 0) with mask-dtype runtime detection.
    // mask[0][0..3] are all 1 (len >= S/2):
    //   uint8/bool -> first word 0x01010101 ; int32 -> 1 ; float32 -> 0x3F800000
    if (warp == 0) {
        unsigned w0 = *reinterpret_cast<const unsigned*>(mask_raw);
        int cnt = 0;
        if (w0 == 0x3F800000u) {
            const float* mb = reinterpret_cast<const float*>(mask_raw) + b * S_;
            for (int t = lane; t < S_; t += 32) cnt += (mb[t] != 0.0f);
        } else if (w0 > 1u) {
            const unsigned char* mb = reinterpret_cast<const unsigned char*>(mask_raw) + b * S_;
            for (int t = lane; t < S_; t += 32) cnt += (mb[t] != 0);
        } else {
            const int* mb = reinterpret_cast<const int*>(mask_raw) + b * S_;
            for (int t = lane; t < S_; t += 32) cnt += (mb[t] != 0);
        }
        int len = warp_sum_i(cnt);
        if (lane == 0) *(int*)&misc[0] = len;
    }
    __syncthreads();
    int len = *(int*)&misc[0];

    // ---- build 256 pair leaves, one thread each (reads from smem fx) ----
    {
        int u = tid;
        int t1 = 2 * u + 1, t2 = 2 * u + 2;
        float* M = Ms + u * MSTR;
        if (t2 <= len - 1) {
            // full pair: P[i][j] = (sum_k E[i][k]*f1[k]*E[k][j]) * f2[j]
            float f1[9], f2[9];
#pragma unroll
            for (int k = 0; k < 9; k++) {
                f1[k] = fx[t1 * L_ + k];
                f2[k] = fx[t2 * L_ + k];
            }
#pragma unroll
            for (int i = 0; i < 9; i++) {
                float tk[9];
#pragma unroll
                for (int k = 0; k < 9; k++) tk[k] = Es[i * 9 + k] * f1[k];
#pragma unroll
                for (int j = 0; j < 9; j++) {
                    float s = tk[0] * Es[0 * 9 + j];
#pragma unroll
                    for (int k = 1; k < 9; k++)
                        s = fmaf(tk[k], Es[k * 9 + j], s);
                    M[i * RSTR + j] = s * f2[j];
                }
            }
        } else if (t1 <= len - 1) {
            // single step: P = M_{t1}
            float f1[9];
#pragma unroll
            for (int k = 0; k < 9; k++) f1[k] = fx[t1 * L_ + k];
#pragma unroll
            for (int i = 0; i < 9; i++)
#pragma unroll
                for (int j = 0; j < 9; j++)
                    M[i * RSTR + j] = Es[i * 9 + j] * f1[j];
        } else {
            // identity
#pragma unroll
            for (int i = 0; i < 9; i++)
#pragma unroll
                for (int j = 0; j < 9; j++)
                    M[i * RSTR + j] = (i == j) ? 1.0f : 0.0f;
        }
        sc[u] = 0;
    }
    __syncthreads();

    // ---- 8 reduction levels ----
    for (int lvl = 1; lvl <= 8; lvl++) {
        int nm = NLEAF >> lvl;
        int half = 1 << (lvl - 1);

        // pass 1: exponent proxy + scale bookkeeping (reads only)
        if (tid < nm) {
            int m = tid;
            int ls = m << lvl, rs = ls + half;
            float pl = Ms[ls * MSTR], pr = Ms[rs * MSTR];
            int ke = (int)((__float_as_uint(pl) >> 23) & 255u)
                   + (int)((__float_as_uint(pr) >> 23) & 255u) - 254;
            ke = max(-120, min(120, ke));
            keA[m] = ke;
            sc[ls] = sc[ls] + sc[rs] + ke;
        }
        __syncthreads();

        // pass 2: row-parallel matmul, in-place into left slot (float4 LDS)
        int items = nm * 9;
        for (int it = tid; it < items; it += 256) {
            int m = it / 9, i = it - m * 9;
            int ls = m << lvl, rs = ls + half;
            float* Lp = Ms + ls * MSTR;
            const float* Rp = Ms + rs * MSTR;
            float lrow[9];
            ldrow9(Lp + i * RSTR, lrow);
            float outr[9];
#pragma unroll
            for (int j = 0; j < 9; j++) outr[j] = 0.f;
#pragma unroll
            for (int k = 0; k < 9; k++) {
                float rrow[9];
                ldrow9(Rp + k * RSTR, rrow);
                float lv = lrow[k];
#pragma unroll
                for (int j = 0; j < 9; j++)
                    outr[j] = fmaf(lv, rrow[j], outr[j]);
            }
            float scale = __uint_as_float((unsigned)(127 - keA[m]) << 23);
#pragma unroll
            for (int j = 0; j < 9; j++) Lp[i * RSTR + j] = outr[j] * scale;
        }
        __syncthreads();
    }

    // ---- final combine (warp 0) + gold score (warp 1) ----
    if (warp == 0) {
        float v = 0.f;
        if (lane < 9) {
            int j = lane;
#pragma unroll
            for (int i = 0; i < 9; i++) {
                float a0 = fx[i] * ex2f(start_t[i] * LOG2E);
                v = fmaf(a0, Ms[i * RSTR + j], v);
            }
            v *= ex2f(end_t[j] * LOG2E);
        }
        float den = warp_sum(v);
        if (lane == 0)
            misc[2] = ((float)sc[0] + lg2f_(den)) * LN2f;   // log_den
    } else if (warp == 1) {
        const float* feats = g_feats + (size_t)b * (S_ * L_);
        const int* lab = labels + b * S_;
        float s = 0.f;
#pragma unroll
        for (int k = 0; k < S_ / 32; k++) {
            int t = k * 32 + lane;
            if (t >= 1 && t < len) {
                int lp = lab[t - 1], lt = lab[t];
                s += trans[lp * L_ + lt] + feats[t * L_ + lt];
            }
        }
        s = warp_sum(s);
        if (lane == 0) {
            int l0 = lab[0];
            int ll = lab[len - 1];
            s += start_t[l0] + feats[l0] + end_t[ll];
            misc[1] = s;
        }
    }
    __syncthreads();

    // ---- fused final mean (threadfence reduction; deterministic order) ----
    if (tid == 0) {
        g_res[b] = misc[2] - misc[1];
        __threadfence();
        unsigned t = atomicAdd(&g_arrive, 1u);
        if (t == B_ - 1) {
            __threadfence();
            float s = 0.f;
#pragma unroll 8
            for (int i = 0; i < B_; i++) s += g_res[i];
            out[0] = s * (1.0f / 64.0f);
            g_arrive = 0;           // reset for next graph replay
            __threadfence();
        }
    }
}

extern "C" void kernel_launch(void* const* d_in, const int* in_sizes, int n_in,
                              void* d_out, int out_size) {
    const float* hidden  = (const float*)d_in[0];
    const float* W       = (const float*)d_in[1];
    const float* bias    = (const float*)d_in[2];
    const float* start_t = (const float*)d_in[3];
    const float* end_t   = (const float*)d_in[4];
    const float* trans   = (const float*)d_in[5];
    const int*   labels  = (const int*)d_in[6];
    const void*  mask    = (const void*)d_in[7];

    // idempotent, non-stream API: safe to call every time (incl. during capture)
    cudaFuncSetAttribute(crf_kernel,
                         cudaFuncAttributeMaxDynamicSharedMemorySize,
                         SMEM_BYTES);

    feats_kernel<<<(B_ * S_) / 32, 256>>>(hidden, W, bias);
    crf_kernel<<<B_, 256, SMEM_BYTES>>>(start_t, end_t, trans, labels, mask,
                                        (float*)d_out);
}

// round 16
// speedup vs baseline: 1.7638x; 1.2163x over previous
#include <cuda_runtime.h>
#include <cstdint>

#define B_ 64
#define S_ 512
#define H_ 768
#define L_ 9
#define NLEAF 256          // pair leaves: leaf u covers steps 2u+1, 2u+2
#define MSTR 85            // matrix stride (floats); 85 mod 32 = 21, coprime -> conflict-free
#define PSTR 257           // partials stride (floats) -> conflict-free smem
#define CRF_THREADS 512
#define LOG2E 1.4426950408889634f
#define LN2f  0.6931471805599453f

// dynamic smem layout for crf_kernel (floats):
//   fx  : 512*9        staged fexp for this batch (coalesced copy-in)
//   Ms  : 256*85       pair/product matrices (9x9, stride-85, scalar access)
//   sc  : 256 ints     renorm exponent accumulators
//   keA : 128 ints     per-level scale factors
//   Es  : 81           exp(trans)
//   misc: [0]=len (int), [1]=score, [2]=log_den
#define SMEM_BYTES (S_ * L_ * 4 + NLEAF * MSTR * 4 + NLEAF * 4 + 128 * 4 + 81 * 4 + 16)

// device scratch (no allocations allowed)
__device__ float g_feats[B_ * S_ * L_];
__device__ float g_fexp [B_ * S_ * L_];
__device__ float g_res  [B_];
__device__ unsigned g_arrive = 0;

__device__ __forceinline__ float ex2f(float x) {
    float y; asm("ex2.approx.f32 %0, %1;" : "=f"(y) : "f"(x)); return y;
}
__device__ __forceinline__ float lg2f_(float x) {
    float y; asm("lg2.approx.f32 %0, %1;" : "=f"(y) : "f"(x)); return y;
}
__device__ __forceinline__ void ffma2(unsigned long long& d,
                                      unsigned long long a,
                                      unsigned long long b) {
    asm("fma.rn.f32x2 %0, %1, %2, %0;" : "+l"(d) : "l"(a), "l"(b));
}
__device__ __forceinline__ float warp_sum(float v) {
    v += __shfl_xor_sync(0xffffffffu, v, 16);
    v += __shfl_xor_sync(0xffffffffu, v, 8);
    v += __shfl_xor_sync(0xffffffffu, v, 4);
    v += __shfl_xor_sync(0xffffffffu, v, 2);
    v += __shfl_xor_sync(0xffffffffu, v, 1);
    return v;
}
__device__ __forceinline__ int warp_sum_i(int v) {
    v += __shfl_xor_sync(0xffffffffu, v, 16);
    v += __shfl_xor_sync(0xffffffffu, v, 8);
    v += __shfl_xor_sync(0xffffffffu, v, 4);
    v += __shfl_xor_sync(0xffffffffu, v, 2);
    v += __shfl_xor_sync(0xffffffffu, v, 1);
    return v;
}

// ---------------------------------------------------------------------------
// K1: feats[b,s,l] = hidden[b,s,:] . W[l,:] + bias[l]; also fexp = exp(feats).
// 2 rows/warp (16 rows/block, grid 2048); W staged to SMEM via float4;
// fma.rn.f32x2 packed FMAs; software-prefetch double buffer.
// __launch_bounds__(256, 2) FORCES <=128 regs => >=2 blocks/SM (16 warps),
// guaranteeing the latency-hiding occupancy the prefetch model assumes.
// Epilogue: SMEM transpose-reduce, fixed-shape tree sums (deterministic).
// ---------------------------------------------------------------------------
__global__ __launch_bounds__(256, 2) void feats_kernel(
        const float* __restrict__ hidden,
        const float* __restrict__ W,
        const float* __restrict__ bias) {
    __shared__ __align__(16) float sbuf[L_ * H_ + 16];  // Ws (6912) >= partials (18*257)
    float* Ws   = sbuf;
    float* part = sbuf;

    int tid = threadIdx.x;
    {   // vectorized W stage: 6912 floats = 1728 float4
        const float4* src = reinterpret_cast<const float4*>(W);
        float4* dst = reinterpret_cast<float4*>(Ws);
        for (int i = tid; i < (L_ * H_) / 4; i += 256) dst[i] = src[i];
    }
    __syncthreads();

    int warp = tid >> 5, lane = tid & 31;
    int rbase = blockIdx.x * 16 + warp * 2;
    const float* row0 = hidden + (size_t)rbase * H_;
    const float* row1 = row0 + H_;

    unsigned long long acc2[2][9];
#pragma unroll
    for (int r = 0; r < 2; r++)
#pragma unroll
        for (int l = 0; l < 9; l++) acc2[r][l] = 0ull;

    int h0 = lane * 4;
    ulonglong2 hv0 = *reinterpret_cast<const ulonglong2*>(row0 + h0);
    ulonglong2 hv1 = *reinterpret_cast<const ulonglong2*>(row1 + h0);

#pragma unroll
    for (int c = 0; c < 6; c++) {
        int h = c * 128 + lane * 4;
        ulonglong2 hn0, hn1;
        if (c < 5) {   // prefetch next chunk before consuming current
            hn0 = *reinterpret_cast<const ulonglong2*>(row0 + h + 128);
            hn1 = *reinterpret_cast<const ulonglong2*>(row1 + h + 128);
        }
#pragma unroll
        for (int l = 0; l < 9; l++) {
            ulonglong2 wv = *reinterpret_cast<const ulonglong2*>(&Ws[l * H_ + h]);
            ffma2(acc2[0][l], hv0.x, wv.x);
            ffma2(acc2[0][l], hv0.y, wv.y);
            ffma2(acc2[1][l], hv1.x, wv.x);
            ffma2(acc2[1][l], hv1.y, wv.y);
        }
        if (c < 5) { hv0 = hn0; hv1 = hn1; }
    }
    __syncthreads();   // done reading Ws; safe to overwrite with partials

#pragma unroll
    for (int r = 0; r < 2; r++)
#pragma unroll
        for (int l = 0; l < 9; l++) {
            float lo = __uint_as_float((unsigned)(acc2[r][l] & 0xffffffffull));
            float hi = __uint_as_float((unsigned)(acc2[r][l] >> 32));
            part[(r * 9 + l) * PSTR + tid] = lo + hi;
        }
    __syncthreads();

    // 144 outputs; thread o sums 32 consecutive lanes (fixed-shape tree:
    // deterministic — identical association every run)
    int o = tid;
    if (o < 144) {
        int w = o / 18, idx = o - w * 18;
        int r = idx / 9, l = idx - r * 9;
        const float* p = part + idx * PSTR + w * 32;
        float g0 = 0.f, g1 = 0.f, g2 = 0.f, g3 = 0.f;
#pragma unroll
        for (int k = 0; k < 8; k++) {
            g0 += p[k];
            g1 += p[8 + k];
            g2 += p[16 + k];
            g3 += p[24 + k];
        }
        float v = ((g0 + g1) + (g2 + g3)) + __ldg(bias + l);
        size_t off = (size_t)(blockIdx.x * 16 + w * 2 + r) * L_ + l;
        g_feats[off] = v;
        g_fexp[off]  = ex2f(v * LOG2E);
    }
}

// ---------------------------------------------------------------------------
// K2: fused CRF via parallel binary tree over PAIR operators + final mean.
// 512 threads (issue-bound work; 1 block/SM either way, extra warps free).
// Leaf u is built by TWO threads: tid = 2u+half, half 0 -> rows 0..4,
// half 1 -> rows 5..8. Conflict-free SMEM: matrices at stride MSTR=85
// (85 mod 32 = 21, coprime with 32); scalar access only.
// Per-matrix base-2 renorm via exponent proxy (read-only pre-pass, race-free).
// log_den = ln( a0^T * root * exp(end) ); warp 1 computes gold-path score.
// Last-arriving block does the mean over g_res (deterministic fixed order).
// ---------------------------------------------------------------------------
__global__ __launch_bounds__(CRF_THREADS) void crf_kernel(
        const float* __restrict__ start_t,
        const float* __restrict__ end_t,
        const float* __restrict__ trans,
        const int*   __restrict__ labels,
        const void*  __restrict__ mask_raw,
        float* __restrict__ out) {
    extern __shared__ __align__(16) float smem[];
    float* fx  = smem;                               // 512*9
    float* Ms  = fx + S_ * L_;                       // 256*85
    int*   sc  = (int*)(Ms + NLEAF * MSTR);          // 256
    int*   keA = sc + NLEAF;                         // 128
    float* Es  = (float*)(keA + 128);                // 81
    float* misc = Es + 81;                           // [0]=len,[1]=score,[2]=lden

    int b = blockIdx.x;
    int tid = threadIdx.x, lane = tid & 31, warp = tid >> 5;
    const float* fexp_b = g_fexp + (size_t)b * (S_ * L_);

    // stage fexp for this batch (coalesced float4)
    {
        const float4* src = reinterpret_cast<const float4*>(fexp_b);
        float4* dst = reinterpret_cast<float4*>(fx);
        for (int i = tid; i < (S_ * L_) / 4; i += CRF_THREADS) dst[i] = src[i];
    }

    // E = exp(trans) (threads 0..80)
    if (tid < 81) Es[tid] = ex2f(trans[tid] * LOG2E);

    // sequence length (warp 0) with mask-dtype runtime detection.
    // mask[0][0..3] are all 1 (len >= S/2):
    //   uint8/bool -> first word 0x01010101 ; int32 -> 1 ; float32 -> 0x3F800000
    if (warp == 0) {
        unsigned w0 = *reinterpret_cast<const unsigned*>(mask_raw);
        int cnt = 0;
        if (w0 == 0x3F800000u) {
            const float* mb = reinterpret_cast<const float*>(mask_raw) + b * S_;
            for (int t = lane; t < S_; t += 32) cnt += (mb[t] != 0.0f);
        } else if (w0 > 1u) {
            const unsigned char* mb = reinterpret_cast<const unsigned char*>(mask_raw) + b * S_;
            for (int t = lane; t < S_; t += 32) cnt += (mb[t] != 0);
        } else {
            const int* mb = reinterpret_cast<const int*>(mask_raw) + b * S_;
            for (int t = lane; t < S_; t += 32) cnt += (mb[t] != 0);
        }
        int len = warp_sum_i(cnt);
        if (lane == 0) *(int*)&misc[0] = len;
    }
    __syncthreads();
    int len = *(int*)&misc[0];

    // ---- build 256 pair leaves, TWO threads each (row split 0..4 / 5..8) ----
    {
        int u = tid >> 1;
        int half = tid & 1;
        int i_beg = half ? 5 : 0;
        int t1 = 2 * u + 1, t2 = 2 * u + 2;
        float* M = Ms + u * MSTR;
        if (t2 <= len - 1) {
            // full pair: P[i][j] = (sum_k E[i][k]*f1[k]*E[k][j]) * f2[j]
            float f1[9], f2[9];
#pragma unroll
            for (int k = 0; k < 9; k++) {
                f1[k] = fx[t1 * L_ + k];
                f2[k] = fx[t2 * L_ + k];
            }
#pragma unroll
            for (int ii = 0; ii < 5; ii++) {
                if (half == 0 || ii < 4) {
                    int i = i_beg + ii;
                    float tk[9];
#pragma unroll
                    for (int k = 0; k < 9; k++) tk[k] = Es[i * 9 + k] * f1[k];
#pragma unroll
                    for (int j = 0; j < 9; j++) {
                        float s = tk[0] * Es[0 * 9 + j];
#pragma unroll
                        for (int k = 1; k < 9; k++)
                            s = fmaf(tk[k], Es[k * 9 + j], s);
                        M[i * 9 + j] = s * f2[j];
                    }
                }
            }
        } else if (t1 <= len - 1) {
            // single step: P = M_{t1}
            float f1[9];
#pragma unroll
            for (int k = 0; k < 9; k++) f1[k] = fx[t1 * L_ + k];
#pragma unroll
            for (int ii = 0; ii < 5; ii++) {
                if (half == 0 || ii < 4) {
                    int i = i_beg + ii;
#pragma unroll
                    for (int j = 0; j < 9; j++)
                        M[i * 9 + j] = Es[i * 9 + j] * f1[j];
                }
            }
        } else {
            // identity
#pragma unroll
            for (int ii = 0; ii < 5; ii++) {
                if (half == 0 || ii < 4) {
                    int i = i_beg + ii;
#pragma unroll
                    for (int j = 0; j < 9; j++)
                        M[i * 9 + j] = (i == j) ? 1.0f : 0.0f;
                }
            }
        }
        if (half == 0) sc[u] = 0;
    }
    __syncthreads();

    // ---- 8 reduction levels ----
    for (int lvl = 1; lvl <= 8; lvl++) {
        int nm = NLEAF >> lvl;
        int half = 1 << (lvl - 1);

        // pass 1: exponent proxy + scale bookkeeping (reads only)
        if (tid < nm) {
            int m = tid;
            int ls = m << lvl, rs = ls + half;
            float pl = Ms[ls * MSTR], pr = Ms[rs * MSTR];
            int ke = (int)((__float_as_uint(pl) >> 23) & 255u)
                   + (int)((__float_as_uint(pr) >> 23) & 255u) - 254;
            ke = max(-120, min(120, ke));
            keA[m] = ke;
            sc[ls] = sc[ls] + sc[rs] + ke;
        }
        __syncthreads();

        // pass 2: row-parallel matmul, in-place into left slot (scalar LDS,
        // conflict-free via MSTR=85; R reads broadcast within same-m lanes)
        int items = nm * 9;
        for (int it = tid; it < items; it += CRF_THREADS) {
            int m = it / 9, i = it - m * 9;
            int ls = m << lvl, rs = ls + half;
            float* Lp = Ms + ls * MSTR;
            const float* Rp = Ms + rs * MSTR;
            float lrow[9];
#pragma unroll
            for (int k = 0; k < 9; k++) lrow[k] = Lp[i * 9 + k];
            float outr[9];
#pragma unroll
            for (int j = 0; j < 9; j++) outr[j] = 0.f;
#pragma unroll
            for (int k = 0; k < 9; k++) {
                float lv = lrow[k];
#pragma unroll
                for (int j = 0; j < 9; j++)
                    outr[j] = fmaf(lv, Rp[k * 9 + j], outr[j]);
            }
            float scale = __uint_as_float((unsigned)(127 - keA[m]) << 23);
#pragma unroll
            for (int j = 0; j < 9; j++) Lp[i * 9 + j] = outr[j] * scale;
        }
        __syncthreads();
    }

    // ---- final combine (warp 0) + gold score (warp 1) ----
    if (warp == 0) {
        float v = 0.f;
        if (lane < 9) {
            int j = lane;
#pragma unroll
            for (int i = 0; i < 9; i++) {
                float a0 = fx[i] * ex2f(start_t[i] * LOG2E);
                v = fmaf(a0, Ms[i * 9 + j], v);
            }
            v *= ex2f(end_t[j] * LOG2E);
        }
        float den = warp_sum(v);
        if (lane == 0)
            misc[2] = ((float)sc[0] + lg2f_(den)) * LN2f;   // log_den
    } else if (warp == 1) {
        const float* feats = g_feats + (size_t)b * (S_ * L_);
        const int* lab = labels + b * S_;
        float s = 0.f;
#pragma unroll
        for (int k = 0; k < S_ / 32; k++) {
            int t = k * 32 + lane;
            if (t >= 1 && t < len) {
                int lp = __ldg(lab + t - 1), lt = __ldg(lab + t);
                s += trans[lp * L_ + lt] + feats[t * L_ + lt];
            }
        }
        s = warp_sum(s);
        if (lane == 0) {
            int l0 = __ldg(lab);
            int ll = __ldg(lab + len - 1);
            s += start_t[l0] + feats[l0] + end_t[ll];
            misc[1] = s;
        }
    }
    __syncthreads();

    // ---- fused final mean (threadfence reduction; deterministic order) ----
    if (tid == 0) {
        g_res[b] = misc[2] - misc[1];
        __threadfence();
        unsigned t = atomicAdd(&g_arrive, 1u);
        if (t == B_ - 1) {
            __threadfence();
            float s = 0.f;
#pragma unroll 8
            for (int i = 0; i < B_; i++) s += g_res[i];
            out[0] = s * (1.0f / 64.0f);
            g_arrive = 0;           // reset for next graph replay
            __threadfence();
        }
    }
}

extern "C" void kernel_launch(void* const* d_in, const int* in_sizes, int n_in,
                              void* d_out, int out_size) {
    const float* hidden  = (const float*)d_in[0];
    const float* W       = (const float*)d_in[1];
    const float* bias    = (const float*)d_in[2];
    const float* start_t = (const float*)d_in[3];
    const float* end_t   = (const float*)d_in[4];
    const float* trans   = (const float*)d_in[5];
    const int*   labels  = (const int*)d_in[6];
    const void*  mask    = (const void*)d_in[7];

    // idempotent, non-stream API: safe to call every time (incl. during capture)
    cudaFuncSetAttribute(crf_kernel,
                         cudaFuncAttributeMaxDynamicSharedMemorySize,
                         SMEM_BYTES);

    feats_kernel<<<(B_ * S_) / 16, 256>>>(hidden, W, bias);
    crf_kernel<<<B_, CRF_THREADS, SMEM_BYTES>>>(start_t, end_t, trans, labels,
                                                mask, (float*)d_out);
}